// round 16
// baseline (speedup 1.0000x reference)
#include <cuda_runtime.h>
#include <cuda_fp16.h>
#include <cstdint>

#define LRELU_ALPHA 0.2f
#define EXP_CLAMP 1000000.0f
#define DENOM_EPS 1e-10f
#define N_NODES 50000
#define N_EDGES 1600000
#define IN_F 128
#define OUT_F 64
#define CAP 128          // bucket capacity per dst (Poisson(32), max ~70)

#define TILE_R 128
#define KC 32
#define HS_PAD 132
#define WS_PAD 68
#define GEMM_SMEM ((KC * HS_PAD + IN_F * WS_PAD) * 4)
#define GEMM_BLOCKS ((N_NODES + TILE_R - 1) / TILE_R)        // 391
#define SCAT_BLOCKS (N_EDGES / 256)                          // 6250 (exact)
#define AGG_BLOCKS  ((N_NODES * 32 + 255) / 256)             // 6250

// Device scratch (no allocation allowed). All statically zero-initialized;
// every field is self-cleaning across graph replays:
//   g_cnt      — reset to 0 by the aggregate warp that owns it
//   g_ovf_flag — fully rewritten by scatter every run
__device__ __half g_Whh[N_NODES * OUT_F];     // fp16 Wh (6.4 MB)
__device__ float g_s[N_NODES];
__device__ float g_t[N_NODES];
__device__ int   g_cnt[N_NODES];
__device__ int   g_bucket[N_NODES * CAP];     // 25.6 MB
__device__ unsigned char g_ovf_flag[N_EDGES]; // 1.6 MB, per-edge overflow bit

// Packed fp32x2 FMA (Blackwell sm_100+)
__device__ __forceinline__ float2 ffma2(float2 a, float2 b, float2 c) {
    float2 d;
    asm("fma.rn.f32x2 %0, %1, %2, %3;"
        : "=l"(*(unsigned long long*)&d)
        : "l"(*(unsigned long long*)&a),
          "l"(*(unsigned long long*)&b),
          "l"(*(unsigned long long*)&c));
    return d;
}

// Per-warp adj dtype detect: read the first 32 odd 32-bit words (2 cached
// lines). int64 adj (indices < 2^31) has all-zero odd words; int32 adj has
// random src indices there — all-zero probability (1/50000)^32 ~ 0.
__device__ __forceinline__ bool detect_adj64(const void* __restrict__ adj, int lane) {
    unsigned probe = ((const unsigned*)adj)[1 + 2 * lane];
    return __ballot_sync(0xffffffffu, probe != 0) == 0;
}

__device__ __forceinline__ void load_edge(const void* __restrict__ adj, bool adj64,
                                          int i, int& dst, int& src) {
    if (adj64) {
        const longlong2* p = (const longlong2*)adj;
        longlong2 v = __ldg(p + i);
        dst = (int)v.x; src = (int)v.y;
    } else {
        const int2* p = (const int2*)adj;
        int2 v = __ldg(p + i);
        dst = v.x; src = v.y;
    }
}

// ---------------------------------------------------------------------------
// Kernel 0 (fused): blocks [0,391) GEMM; blocks [391, 6641) bucket scatter.
// ---------------------------------------------------------------------------
__global__ __launch_bounds__(256) void gs_kernel(const float* __restrict__ h,
                                                 const float* __restrict__ W,
                                                 const float* __restrict__ a,
                                                 const void* __restrict__ adj) {
    if (blockIdx.x >= GEMM_BLOCKS) {
        // ---- scatter: bin src by dst; per-edge overflow flag (no counter)
        bool adj64 = detect_adj64(adj, threadIdx.x & 31);
        int i = (blockIdx.x - GEMM_BLOCKS) * 256 + threadIdx.x;   // always < N_EDGES
        int dst, src;
        load_edge(adj, adj64, i, dst, src);
        int c = atomicAdd(g_cnt + dst, 1);
        bool ov = (c >= CAP);
        g_ovf_flag[i] = ov;
        if (!ov) g_bucket[(size_t)dst * CAP + c] = src;
        return;
    }

    // ---- GEMM: Wh = h @ W (fp16 out) with fused s/t projection ----
    extern __shared__ float smem[];
    float* hs = smem;                         // [KC][HS_PAD] transposed h chunk
    float* Ws = smem + KC * HS_PAD;           // [IN_F][WS_PAD]

    int tid = threadIdx.x;
    for (int i = tid; i < IN_F * OUT_F; i += 256) {
        int k = i >> 6, c = i & 63;
        Ws[k * WS_PAD + c] = W[i];
    }

    int colg = tid & 15;
    int rowg = tid >> 4;
    int c0 = colg * 4;
    int r0 = rowg * 8;
    int R0 = blockIdx.x * TILE_R;

    float2 acc[4][4];
    #pragma unroll
    for (int p = 0; p < 4; p++)
        #pragma unroll
        for (int j = 0; j < 4; j++)
            acc[p][j] = make_float2(0.f, 0.f);

    for (int kc = 0; kc < IN_F; kc += KC) {
        __syncthreads();
        #pragma unroll
        for (int it = 0; it < (TILE_R * KC / 4) / 256; it++) {
            int i   = tid + it * 256;
            int row = i >> 3;
            int k4  = i & 7;
            int gr  = R0 + row;
            if (gr >= N_NODES) gr = 0;
            float4 v = *(const float4*)(h + (size_t)gr * IN_F + kc + k4 * 4);
            hs[(k4 * 4 + 0) * HS_PAD + row] = v.x;
            hs[(k4 * 4 + 1) * HS_PAD + row] = v.y;
            hs[(k4 * 4 + 2) * HS_PAD + row] = v.z;
            hs[(k4 * 4 + 3) * HS_PAD + row] = v.w;
        }
        __syncthreads();

        #pragma unroll 8
        for (int k = 0; k < KC; k++) {
            float4 A = *(const float4*)(hs + k * HS_PAD + r0);
            float4 B = *(const float4*)(hs + k * HS_PAD + r0 + 4);
            float2 hp[4] = { make_float2(A.x, A.y), make_float2(A.z, A.w),
                             make_float2(B.x, B.y), make_float2(B.z, B.w) };
            float4 wv = *(const float4*)(Ws + (kc + k) * WS_PAD + c0);
            float2 w0 = make_float2(wv.x, wv.x);
            float2 w1 = make_float2(wv.y, wv.y);
            float2 w2 = make_float2(wv.z, wv.z);
            float2 w3 = make_float2(wv.w, wv.w);
            #pragma unroll
            for (int p = 0; p < 4; p++) {
                acc[p][0] = ffma2(hp[p], w0, acc[p][0]);
                acc[p][1] = ffma2(hp[p], w1, acc[p][1]);
                acc[p][2] = ffma2(hp[p], w2, acc[p][2]);
                acc[p][3] = ffma2(hp[p], w3, acc[p][3]);
            }
        }
    }

    // Store Wh in fp16 (4 cols per row, 8 rows per thread)
    #pragma unroll
    for (int p = 0; p < 4; p++) {
        int r = R0 + r0 + 2 * p;
        if (r < N_NODES) {
            __half2 h01 = __floats2half2_rn(acc[p][0].x, acc[p][1].x);
            __half2 h23 = __floats2half2_rn(acc[p][2].x, acc[p][3].x);
            uint2 u; u.x = *(unsigned*)&h01; u.y = *(unsigned*)&h23;
            *(uint2*)(g_Whh + (size_t)r * OUT_F + c0) = u;
        }
        if (r + 1 < N_NODES) {
            __half2 h01 = __floats2half2_rn(acc[p][0].y, acc[p][1].y);
            __half2 h23 = __floats2half2_rn(acc[p][2].y, acc[p][3].y);
            uint2 u; u.x = *(unsigned*)&h01; u.y = *(unsigned*)&h23;
            *(uint2*)(g_Whh + (size_t)(r + 1) * OUT_F + c0) = u;
        }
    }

    // Fused s/t projection (fp32 accumulators)
    float2 sp[4], tp[4];
    #pragma unroll
    for (int p = 0; p < 4; p++) { sp[p] = make_float2(0.f, 0.f); tp[p] = make_float2(0.f, 0.f); }
    #pragma unroll
    for (int j = 0; j < 4; j++) {
        float a1v = a[c0 + j];
        float a2v = a[OUT_F + c0 + j];
        float2 a1d = make_float2(a1v, a1v);
        float2 a2d = make_float2(a2v, a2v);
        #pragma unroll
        for (int p = 0; p < 4; p++) {
            sp[p] = ffma2(acc[p][j], a1d, sp[p]);
            tp[p] = ffma2(acc[p][j], a2d, tp[p]);
        }
    }
    #pragma unroll
    for (int o = 8; o > 0; o >>= 1) {
        #pragma unroll
        for (int p = 0; p < 4; p++) {
            sp[p].x += __shfl_down_sync(0xffffffffu, sp[p].x, o, 16);
            sp[p].y += __shfl_down_sync(0xffffffffu, sp[p].y, o, 16);
            tp[p].x += __shfl_down_sync(0xffffffffu, tp[p].x, o, 16);
            tp[p].y += __shfl_down_sync(0xffffffffu, tp[p].y, o, 16);
        }
    }
    if (colg == 0) {
        #pragma unroll
        for (int p = 0; p < 4; p++) {
            int r = R0 + r0 + 2 * p;
            if (r < N_NODES)     { g_s[r]     = sp[p].x; g_t[r]     = tp[p].x; }
            if (r + 1 < N_NODES) { g_s[r + 1] = sp[p].y; g_t[r + 1] = tp[p].y; }
        }
    }
}

// ---------------------------------------------------------------------------
// Kernel 1 (hot): one warp per dst node. Half-warp per edge; inner loop
// consumes TWO stage entries per iteration via one LDS.128. Overflow edges
// (degree > CAP; never on this data) recovered by scanning flags+adj.
// Self-cleans g_cnt for the next graph replay.
// ---------------------------------------------------------------------------
__global__ __launch_bounds__(256) void aggregate_kernel(float* __restrict__ out,
                                                        const void* __restrict__ adj) {
    __shared__ float2 stage_s[8][32];
    int wl   = threadIdx.x >> 5;
    int warp = (blockIdx.x * blockDim.x + threadIdx.x) >> 5;
    int lane = threadIdx.x & 31;
    if (warp >= N_NODES) return;
    int d = warp;
    int n_full = g_cnt[d];
    if (lane == 0) g_cnt[d] = 0;        // self-clean for next replay
    int n = (n_full > CAP) ? CAP : n_full;

    int half    = lane >> 4;            // 0 or 1: which pair-slot of each quad
    int sublane = lane & 15;            // owns cols [4*sublane, 4*sublane+4)

    float sd = g_s[d];
    const int* bkt = g_bucket + (size_t)d * CAP;
    const char* whbase = (const char*)g_Whh + sublane * 8;
    float2* stg = stage_s[wl];

    float2 acc0 = make_float2(0.f, 0.f);   // cols 4s+0,4s+1
    float2 acc1 = make_float2(0.f, 0.f);   // cols 4s+2,4s+3
    float xsum = 0.f;

    for (int base = 0; base < n; base += 32) {
        int i = base + lane;
        float x = 0.f;
        int off = 0;                       // pad: row 0, x=0 -> harmless
        if (i < n) {
            int src = __ldg(bkt + i);
            float e = sd + __ldg(g_t + src);
            e = (e > 0.0f) ? e : LRELU_ALPHA * e;
            x = fminf(__expf(e), EXP_CLAMP);
            xsum += x;
            off = src << 7;                // src * 128 bytes (fp16 row)
        }
        stg[lane] = make_float2(x, __int_as_float(off));
        __syncwarp();

        int m = n - base; if (m > 32) m = 32;
        int mm = (m + 3) & ~3;             // padded entries have x=0
        #pragma unroll 2
        for (int j = half * 2; j < mm; j += 4) {
            float4 pq = *(const float4*)(stg + j);   // edges j, j+1
            uint2 wv0 = *(const uint2*)(whbase + __float_as_int(pq.y));
            uint2 wv1 = *(const uint2*)(whbase + __float_as_int(pq.w));
            float2 xx0 = make_float2(pq.x, pq.x);
            float2 xx1 = make_float2(pq.z, pq.z);
            acc0 = ffma2(xx0, __half22float2(*(__half2*)&wv0.x), acc0);
            acc1 = ffma2(xx0, __half22float2(*(__half2*)&wv0.y), acc1);
            acc0 = ffma2(xx1, __half22float2(*(__half2*)&wv1.x), acc0);
            acc1 = ffma2(xx1, __half22float2(*(__half2*)&wv1.y), acc1);
        }
        __syncwarp();
    }

    // Overflow path (degree > CAP; never on this data): scan flags + adj.
    if (n_full > CAP) {
        bool adj64 = detect_adj64(adj, lane);
        for (int base = 0; base < N_EDGES; base += 32) {
            int i = base + lane;
            float x = 0.f;
            int off = 0;
            if (g_ovf_flag[i]) {
                int dd, ss;
                load_edge(adj, adj64, i, dd, ss);
                if (dd == d) {
                    float ev = sd + __ldg(g_t + ss);
                    ev = (ev > 0.0f) ? ev : LRELU_ALPHA * ev;
                    x = fminf(__expf(ev), EXP_CLAMP);
                    xsum += x;
                    off = ss << 7;
                }
            }
            stg[lane] = make_float2(x, __int_as_float(off));
            __syncwarp();

            #pragma unroll 2
            for (int j = half * 2; j < 32; j += 4) {
                float4 pq = *(const float4*)(stg + j);
                uint2 wv0 = *(const uint2*)(whbase + __float_as_int(pq.y));
                uint2 wv1 = *(const uint2*)(whbase + __float_as_int(pq.w));
                float2 xx0 = make_float2(pq.x, pq.x);
                float2 xx1 = make_float2(pq.z, pq.z);
                acc0 = ffma2(xx0, __half22float2(*(__half2*)&wv0.x), acc0);
                acc1 = ffma2(xx0, __half22float2(*(__half2*)&wv0.y), acc1);
                acc0 = ffma2(xx1, __half22float2(*(__half2*)&wv1.x), acc0);
                acc1 = ffma2(xx1, __half22float2(*(__half2*)&wv1.y), acc1);
            }
            __syncwarp();
        }
    }

    // fold the second half-warp into lanes 0-15
    acc0.x += __shfl_down_sync(0xffffffffu, acc0.x, 16);
    acc0.y += __shfl_down_sync(0xffffffffu, acc0.y, 16);
    acc1.x += __shfl_down_sync(0xffffffffu, acc1.x, 16);
    acc1.y += __shfl_down_sync(0xffffffffu, acc1.y, 16);

    #pragma unroll
    for (int o = 16; o > 0; o >>= 1)
        xsum += __shfl_xor_sync(0xffffffffu, xsum, o);

    if (half == 0) {
        float4* po = (float4*)(out + (size_t)d * OUT_F) + sublane;
        float r = __frcp_rn(xsum + DENOM_EPS);
        float v0 = acc0.x * r, v1 = acc0.y * r;
        float v2 = acc1.x * r, v3 = acc1.y * r;
        v0 = (v0 > 0.0f) ? v0 : expm1f(v0);
        v1 = (v1 > 0.0f) ? v1 : expm1f(v1);
        v2 = (v2 > 0.0f) ? v2 : expm1f(v2);
        v3 = (v3 > 0.0f) ? v3 : expm1f(v3);
        *po = make_float4(v0, v1, v2, v3);
    }
}

// ---------------------------------------------------------------------------
extern "C" void kernel_launch(void* const* d_in, const int* in_sizes, int n_in,
                              void* d_out, int out_size) {
    const float* h   = (const float*)d_in[0];   // [50000, 128]
    const float* W   = (const float*)d_in[1];   // [128, 64]
    const float* a   = (const float*)d_in[2];   // [128, 1]
    const void*  adj = d_in[3];                 // [1.6M, 2] int32 or int64
    float* out = (float*)d_out;                 // [50000, 64]

    static bool smem_set = false;
    if (!smem_set) {
        cudaFuncSetAttribute(gs_kernel,
                             cudaFuncAttributeMaxDynamicSharedMemorySize, GEMM_SMEM);
        smem_set = true;
    }

    gs_kernel<<<GEMM_BLOCKS + SCAT_BLOCKS, 256, GEMM_SMEM>>>(h, W, a, adj);    // idx 0
    aggregate_kernel<<<AGG_BLOCKS, 256>>>(out, adj);                           // idx 1
}

// round 17
// speedup vs baseline: 2.1701x; 2.1701x over previous
#include <cuda_runtime.h>
#include <cuda_fp16.h>
#include <cstdint>

#define LRELU_ALPHA 0.2f
#define EXP_CLAMP 1000000.0f
#define DENOM_EPS 1e-10f
#define N_NODES 50000
#define N_EDGES 1600000
#define IN_F 128
#define OUT_F 64
#define CAP 128          // bucket capacity per dst (Poisson(32), max ~70)

#define TILE_R 128
#define KC 32
#define HS_PAD 132
#define WS_PAD 68
#define GEMM_SMEM ((KC * HS_PAD + IN_F * WS_PAD) * 4)
#define GEMM_BLOCKS ((N_NODES + TILE_R - 1) / TILE_R)        // 391
#define SCAT_BLOCKS (N_EDGES / 2 / 256)                      // 3125 (2 edges/thread)
#define AGG_BLOCKS  ((N_NODES * 32 + 255) / 256)             // 6250

// Device scratch (no allocation allowed in kernel_launch)
__device__ __half g_Whh[N_NODES * OUT_F];     // fp16 Wh (6.4 MB)
__device__ float g_s[N_NODES];
__device__ float g_t[N_NODES];
__device__ int   g_cnt[N_NODES];
__device__ int   g_bucket[N_NODES * CAP];     // 25.6 MB
__device__ int   g_ovf_cnt;
__device__ int2  g_ovf[N_EDGES];              // 12.8 MB — can hold ALL edges
__device__ int   g_adj64;

// Packed fp32x2 FMA (Blackwell sm_100+)
__device__ __forceinline__ float2 ffma2(float2 a, float2 b, float2 c) {
    float2 d;
    asm("fma.rn.f32x2 %0, %1, %2, %3;"
        : "=l"(*(unsigned long long*)&d)
        : "l"(*(unsigned long long*)&a),
          "l"(*(unsigned long long*)&b),
          "l"(*(unsigned long long*)&c));
    return d;
}

// ---------------------------------------------------------------------------
// Kernel 0: init (cnt=0 vectorized, ovf_cnt=0) + cheap adj dtype detect:
// ONE strided LDG per lane over the first 32 odd 32-bit words. int64 adj
// (indices < 2^31) has all-zero odd words; int32 adj has 32 random src
// indices there — all-zero probability (1/50000)^32 ~ 0.
// ---------------------------------------------------------------------------
__global__ void init_kernel(const unsigned int* __restrict__ adj_raw) {
    int i = blockIdx.x * blockDim.x + threadIdx.x;
    if (i < N_NODES / 4)
        ((int4*)g_cnt)[i] = make_int4(0, 0, 0, 0);
    if (i == 0) g_ovf_cnt = 0;

    if (blockIdx.x == 0 && threadIdx.x < 32) {
        unsigned int acc = adj_raw[1 + 2 * threadIdx.x];
        #pragma unroll
        for (int o = 16; o > 0; o >>= 1)
            acc |= __shfl_down_sync(0xffffffffu, acc, o);
        if (threadIdx.x == 0) g_adj64 = (acc == 0) ? 1 : 0;
    }
}

// ---------------------------------------------------------------------------
// Kernel 1 (fused): blocks [0,391) GEMM; blocks [391, 391+3125) scatter,
// TWO edges per thread (int32: one LDG.128 covers both).
// ---------------------------------------------------------------------------
__global__ __launch_bounds__(256) void gs_kernel(const float* __restrict__ h,
                                                 const float* __restrict__ W,
                                                 const float* __restrict__ a,
                                                 const void* __restrict__ adj) {
    if (blockIdx.x >= GEMM_BLOCKS) {
        // ---- scatter: bin src by dst; excess edges go to the overflow list
        int i = (blockIdx.x - GEMM_BLOCKS) * 256 + threadIdx.x;  // pair index
        int d0, s0, d1, s1;
        if (g_adj64) {
            longlong2 v0 = __ldg((const longlong2*)adj + 2 * i);
            longlong2 v1 = __ldg((const longlong2*)adj + 2 * i + 1);
            d0 = (int)v0.x; s0 = (int)v0.y;
            d1 = (int)v1.x; s1 = (int)v1.y;
        } else {
            int4 v = __ldg((const int4*)adj + i);
            d0 = v.x; s0 = v.y; d1 = v.z; s1 = v.w;
        }
        int c0 = atomicAdd(g_cnt + d0, 1);
        if (c0 < CAP) {
            g_bucket[(size_t)d0 * CAP + c0] = s0;
        } else {
            int p = atomicAdd(&g_ovf_cnt, 1);
            g_ovf[p] = make_int2(d0, s0);
        }
        int c1 = atomicAdd(g_cnt + d1, 1);
        if (c1 < CAP) {
            g_bucket[(size_t)d1 * CAP + c1] = s1;
        } else {
            int p = atomicAdd(&g_ovf_cnt, 1);
            g_ovf[p] = make_int2(d1, s1);
        }
        return;
    }

    // ---- GEMM: Wh = h @ W (fp16 out) with fused s/t projection ----
    extern __shared__ float smem[];
    float* hs = smem;                         // [KC][HS_PAD] transposed h chunk
    float* Ws = smem + KC * HS_PAD;           // [IN_F][WS_PAD]

    int tid = threadIdx.x;
    for (int i = tid; i < IN_F * OUT_F; i += 256) {
        int k = i >> 6, c = i & 63;
        Ws[k * WS_PAD + c] = W[i];
    }

    int colg = tid & 15;
    int rowg = tid >> 4;
    int c0 = colg * 4;
    int r0 = rowg * 8;
    int R0 = blockIdx.x * TILE_R;

    float2 acc[4][4];
    #pragma unroll
    for (int p = 0; p < 4; p++)
        #pragma unroll
        for (int j = 0; j < 4; j++)
            acc[p][j] = make_float2(0.f, 0.f);

    for (int kc = 0; kc < IN_F; kc += KC) {
        __syncthreads();
        #pragma unroll
        for (int it = 0; it < (TILE_R * KC / 4) / 256; it++) {
            int i   = tid + it * 256;
            int row = i >> 3;
            int k4  = i & 7;
            int gr  = R0 + row;
            if (gr >= N_NODES) gr = 0;
            float4 v = *(const float4*)(h + (size_t)gr * IN_F + kc + k4 * 4);
            hs[(k4 * 4 + 0) * HS_PAD + row] = v.x;
            hs[(k4 * 4 + 1) * HS_PAD + row] = v.y;
            hs[(k4 * 4 + 2) * HS_PAD + row] = v.z;
            hs[(k4 * 4 + 3) * HS_PAD + row] = v.w;
        }
        __syncthreads();

        #pragma unroll 8
        for (int k = 0; k < KC; k++) {
            float4 A = *(const float4*)(hs + k * HS_PAD + r0);
            float4 B = *(const float4*)(hs + k * HS_PAD + r0 + 4);
            float2 hp[4] = { make_float2(A.x, A.y), make_float2(A.z, A.w),
                             make_float2(B.x, B.y), make_float2(B.z, B.w) };
            float4 wv = *(const float4*)(Ws + (kc + k) * WS_PAD + c0);
            float2 w0 = make_float2(wv.x, wv.x);
            float2 w1 = make_float2(wv.y, wv.y);
            float2 w2 = make_float2(wv.z, wv.z);
            float2 w3 = make_float2(wv.w, wv.w);
            #pragma unroll
            for (int p = 0; p < 4; p++) {
                acc[p][0] = ffma2(hp[p], w0, acc[p][0]);
                acc[p][1] = ffma2(hp[p], w1, acc[p][1]);
                acc[p][2] = ffma2(hp[p], w2, acc[p][2]);
                acc[p][3] = ffma2(hp[p], w3, acc[p][3]);
            }
        }
    }

    // Store Wh in fp16 (4 cols per row, 8 rows per thread)
    #pragma unroll
    for (int p = 0; p < 4; p++) {
        int r = R0 + r0 + 2 * p;
        if (r < N_NODES) {
            __half2 h01 = __floats2half2_rn(acc[p][0].x, acc[p][1].x);
            __half2 h23 = __floats2half2_rn(acc[p][2].x, acc[p][3].x);
            uint2 u; u.x = *(unsigned*)&h01; u.y = *(unsigned*)&h23;
            *(uint2*)(g_Whh + (size_t)r * OUT_F + c0) = u;
        }
        if (r + 1 < N_NODES) {
            __half2 h01 = __floats2half2_rn(acc[p][0].y, acc[p][1].y);
            __half2 h23 = __floats2half2_rn(acc[p][2].y, acc[p][3].y);
            uint2 u; u.x = *(unsigned*)&h01; u.y = *(unsigned*)&h23;
            *(uint2*)(g_Whh + (size_t)(r + 1) * OUT_F + c0) = u;
        }
    }

    // Fused s/t projection (fp32 accumulators)
    float2 sp[4], tp[4];
    #pragma unroll
    for (int p = 0; p < 4; p++) { sp[p] = make_float2(0.f, 0.f); tp[p] = make_float2(0.f, 0.f); }
    #pragma unroll
    for (int j = 0; j < 4; j++) {
        float a1v = a[c0 + j];
        float a2v = a[OUT_F + c0 + j];
        float2 a1d = make_float2(a1v, a1v);
        float2 a2d = make_float2(a2v, a2v);
        #pragma unroll
        for (int p = 0; p < 4; p++) {
            sp[p] = ffma2(acc[p][j], a1d, sp[p]);
            tp[p] = ffma2(acc[p][j], a2d, tp[p]);
        }
    }
    #pragma unroll
    for (int o = 8; o > 0; o >>= 1) {
        #pragma unroll
        for (int p = 0; p < 4; p++) {
            sp[p].x += __shfl_down_sync(0xffffffffu, sp[p].x, o, 16);
            sp[p].y += __shfl_down_sync(0xffffffffu, sp[p].y, o, 16);
            tp[p].x += __shfl_down_sync(0xffffffffu, tp[p].x, o, 16);
            tp[p].y += __shfl_down_sync(0xffffffffu, tp[p].y, o, 16);
        }
    }
    if (colg == 0) {
        #pragma unroll
        for (int p = 0; p < 4; p++) {
            int r = R0 + r0 + 2 * p;
            if (r < N_NODES)     { g_s[r]     = sp[p].x; g_t[r]     = tp[p].x; }
            if (r + 1 < N_NODES) { g_s[r + 1] = sp[p].y; g_t[r + 1] = tp[p].y; }
        }
    }
}

// ---------------------------------------------------------------------------
// Kernel 2 (hot): one warp per dst node. Half-warp per edge; inner loop
// consumes TWO stage entries per iteration via one LDS.128.
// Overflow edges handled by list scan (never taken; correctness-only).
// ---------------------------------------------------------------------------
__global__ __launch_bounds__(256) void aggregate_kernel(float* __restrict__ out) {
    __shared__ float2 stage_s[8][32];
    int wl   = threadIdx.x >> 5;
    int warp = (blockIdx.x * blockDim.x + threadIdx.x) >> 5;
    int lane = threadIdx.x & 31;
    if (warp >= N_NODES) return;
    int d = warp;
    int n_full = g_cnt[d];
    int n = (n_full > CAP) ? CAP : n_full;

    int half    = lane >> 4;            // 0 or 1: which pair-slot of each quad
    int sublane = lane & 15;            // owns cols [4*sublane, 4*sublane+4)

    float sd = g_s[d];
    const int* bkt = g_bucket + (size_t)d * CAP;
    const char* whbase = (const char*)g_Whh + sublane * 8;
    float2* stg = stage_s[wl];

    float2 acc0 = make_float2(0.f, 0.f);   // cols 4s+0,4s+1
    float2 acc1 = make_float2(0.f, 0.f);   // cols 4s+2,4s+3
    float xsum = 0.f;

    for (int base = 0; base < n; base += 32) {
        int i = base + lane;
        float x = 0.f;
        int off = 0;                       // pad: row 0, x=0 -> harmless
        if (i < n) {
            int src = __ldg(bkt + i);
            float e = sd + __ldg(g_t + src);
            e = (e > 0.0f) ? e : LRELU_ALPHA * e;
            x = fminf(__expf(e), EXP_CLAMP);
            xsum += x;
            off = src << 7;                // src * 128 bytes (fp16 row)
        }
        stg[lane] = make_float2(x, __int_as_float(off));
        __syncwarp();

        int m = n - base; if (m > 32) m = 32;
        int mm = (m + 3) & ~3;             // padded entries have x=0
        #pragma unroll 2
        for (int j = half * 2; j < mm; j += 4) {
            float4 pq = *(const float4*)(stg + j);   // edges j, j+1
            uint2 wv0 = *(const uint2*)(whbase + __float_as_int(pq.y));
            uint2 wv1 = *(const uint2*)(whbase + __float_as_int(pq.w));
            float2 xx0 = make_float2(pq.x, pq.x);
            float2 xx1 = make_float2(pq.z, pq.z);
            acc0 = ffma2(xx0, __half22float2(*(__half2*)&wv0.x), acc0);
            acc1 = ffma2(xx0, __half22float2(*(__half2*)&wv0.y), acc1);
            acc0 = ffma2(xx1, __half22float2(*(__half2*)&wv1.x), acc0);
            acc1 = ffma2(xx1, __half22float2(*(__half2*)&wv1.y), acc1);
        }
        __syncwarp();
    }

    // Overflow path (degree > CAP; never on this data): scan global list.
    if (n_full > CAP) {
        int nov = g_ovf_cnt;
        for (int base = 0; base < nov; base += 32) {
            int i = base + lane;
            float x = 0.f;
            int off = 0;
            if (i < nov) {
                int2 e = g_ovf[i];
                if (e.x == d) {
                    float ev = sd + __ldg(g_t + e.y);
                    ev = (ev > 0.0f) ? ev : LRELU_ALPHA * ev;
                    x = fminf(__expf(ev), EXP_CLAMP);
                    xsum += x;
                    off = e.y << 7;
                }
            }
            stg[lane] = make_float2(x, __int_as_float(off));
            __syncwarp();

            int m = nov - base; if (m > 32) m = 32;
            int mm = (m + 3) & ~3;
            for (int j = half * 2; j < mm; j += 4) {
                float4 pq = *(const float4*)(stg + j);
                uint2 wv0 = *(const uint2*)(whbase + __float_as_int(pq.y));
                uint2 wv1 = *(const uint2*)(whbase + __float_as_int(pq.w));
                float2 xx0 = make_float2(pq.x, pq.x);
                float2 xx1 = make_float2(pq.z, pq.z);
                acc0 = ffma2(xx0, __half22float2(*(__half2*)&wv0.x), acc0);
                acc1 = ffma2(xx0, __half22float2(*(__half2*)&wv0.y), acc1);
                acc0 = ffma2(xx1, __half22float2(*(__half2*)&wv1.x), acc0);
                acc1 = ffma2(xx1, __half22float2(*(__half2*)&wv1.y), acc1);
            }
            __syncwarp();
        }
    }

    // fold the second half-warp into lanes 0-15
    acc0.x += __shfl_down_sync(0xffffffffu, acc0.x, 16);
    acc0.y += __shfl_down_sync(0xffffffffu, acc0.y, 16);
    acc1.x += __shfl_down_sync(0xffffffffu, acc1.x, 16);
    acc1.y += __shfl_down_sync(0xffffffffu, acc1.y, 16);

    #pragma unroll
    for (int o = 16; o > 0; o >>= 1)
        xsum += __shfl_xor_sync(0xffffffffu, xsum, o);

    if (half == 0) {
        float4* po = (float4*)(out + (size_t)d * OUT_F) + sublane;
        float r = __frcp_rn(xsum + DENOM_EPS);
        float v0 = acc0.x * r, v1 = acc0.y * r;
        float v2 = acc1.x * r, v3 = acc1.y * r;
        v0 = (v0 > 0.0f) ? v0 : expm1f(v0);
        v1 = (v1 > 0.0f) ? v1 : expm1f(v1);
        v2 = (v2 > 0.0f) ? v2 : expm1f(v2);
        v3 = (v3 > 0.0f) ? v3 : expm1f(v3);
        *po = make_float4(v0, v1, v2, v3);
    }
}

// ---------------------------------------------------------------------------
extern "C" void kernel_launch(void* const* d_in, const int* in_sizes, int n_in,
                              void* d_out, int out_size) {
    const float* h   = (const float*)d_in[0];   // [50000, 128]
    const float* W   = (const float*)d_in[1];   // [128, 64]
    const float* a   = (const float*)d_in[2];   // [128, 1]
    const void*  adj = d_in[3];                 // [1.6M, 2] int32 or int64
    float* out = (float*)d_out;                 // [50000, 64]

    const int T = 256;

    static bool smem_set = false;
    if (!smem_set) {
        cudaFuncSetAttribute(gs_kernel,
                             cudaFuncAttributeMaxDynamicSharedMemorySize, GEMM_SMEM);
        smem_set = true;
    }

    init_kernel<<<(N_NODES / 4 + T - 1) / T, T>>>((const unsigned int*)adj);   // idx 0
    gs_kernel<<<GEMM_BLOCKS + SCAT_BLOCKS, 256, GEMM_SMEM>>>(h, W, a, adj);    // idx 1
    aggregate_kernel<<<AGG_BLOCKS, T>>>(out);                                  // idx 2
}